// round 10
// baseline (speedup 1.0000x reference)
#include <cuda_runtime.h>

// ---------------- problem constants ----------------
#define SB    2304          // S = H*W
#define BSR   4608          // B*S
#define DD    64
#define NHH   8
#define FFD   2048
#define NLAYER 8
#define KS    21
#define KK2   441
#define HH    48
#define WWD   48
#define CC    3
#define BB    2
#define EPSV  1e-5f
#define ZSPL  8

typedef unsigned long long u64;

// ---------------- scratch ----------------
__device__ float g_y[BSR * DD];
__device__ float g_qkv[BSR * 3 * DD];
__device__ float g_attno[BSR * DD];
__device__ float g_part[ZSPL * BSR * DD];
__device__ float g_ff[BSR * FFD];

// ---------------- packed f32x2 helpers ----------------
__device__ __forceinline__ u64 fma2(u64 a, u64 b, u64 c) {
    u64 d;
    asm("fma.rn.f32x2 %0, %1, %2, %3;" : "=l"(d) : "l"(a), "l"(b), "l"(c));
    return d;
}
__device__ __forceinline__ u64 mul2(u64 a, u64 b) {
    u64 d;
    asm("mul.rn.f32x2 %0, %1, %2;" : "=l"(d) : "l"(a), "l"(b));
    return d;
}
__device__ __forceinline__ u64 pack2(float lo, float hi) {
    u64 d;
    asm("mov.b64 %0, {%1, %2};" : "=l"(d) : "r"(__float_as_uint(lo)), "r"(__float_as_uint(hi)));
    return d;
}
__device__ __forceinline__ void unpack2(u64 v, float& lo, float& hi) {
    unsigned a, b;
    asm("mov.b64 {%0, %1}, %2;" : "=r"(a), "=r"(b) : "l"(v));
    lo = __uint_as_float(a); hi = __uint_as_float(b);
}
__device__ __forceinline__ float ex2f(float x) {
    float r;
    asm("ex2.approx.f32 %0, %1;" : "=f"(r) : "f"(x));
    return r;
}

// ---------------- conv 3x3 + BN + ReLU -> [B,S,D] ----------------
__global__ __launch_bounds__(256) void conv_bn_relu(
    const float* __restrict__ x, const float* __restrict__ w,
    const float* __restrict__ cb, const float* __restrict__ gma,
    const float* __restrict__ bta, const float* __restrict__ mean,
    const float* __restrict__ var, float* __restrict__ y)
{
    int idx = blockIdx.x * 256 + threadIdx.x;
    if (idx >= BSR * DD) return;
    int d = idx & 63;
    int s = (idx >> 6) % SB;
    int b = idx / (SB * DD);
    int hh = s / WWD, ww = s % WWD;
    float sum = cb[d];
    #pragma unroll
    for (int ci = 0; ci < 3; ci++) {
        #pragma unroll
        for (int kh = 0; kh < 3; kh++) {
            int ih = hh + kh - 1;
            if ((unsigned)ih >= HH) continue;
            #pragma unroll
            for (int kw = 0; kw < 3; kw++) {
                int iw = ww + kw - 1;
                if ((unsigned)iw >= WWD) continue;
                sum += x[((b * CC + ci) * HH + ih) * WWD + iw] *
                       w[((d * CC + ci) * 3 + kh) * 3 + kw];
            }
        }
    }
    sum = (sum - mean[d]) * rsqrtf(var[d] + EPSV) * gma[d] + bta[d];
    y[idx] = fmaxf(sum, 0.0f);
}

// ============================================================================
// gemm64: C[M,N] = A[M,64] @ W[N,64]^T + bias.  256 threads, 64x64 tile,
// 4x4 per-thread. W staged pre-duplicated as u64 (no pack in inner loop).
// ============================================================================
template<int RELU>
__global__ __launch_bounds__(256) void gemm64(
    const float* __restrict__ A, const float* __restrict__ W,
    const float* __restrict__ bias, float* __restrict__ C, int N)
{
    __shared__ __align__(16) float As[64][68];
    __shared__ __align__(16) u64  Wd[64][66];
    int tid = threadIdx.x;
    int rowBase = blockIdx.y * 64;
    int nBase = blockIdx.x * 64;

    int r = tid >> 2, qd = tid & 3;
    {
        const float* ap = A + (rowBase + r) * 64 + qd * 4;
        #pragma unroll
        for (int j = 0; j < 4; j++) {
            float4 v = *(const float4*)(ap + j * 16);
            int k = qd * 4 + j * 16;
            As[k][r] = v.x; As[k + 1][r] = v.y; As[k + 2][r] = v.z; As[k + 3][r] = v.w;
        }
        int n = nBase + r;
        if (n < N) {
            const float* wp = W + n * 64 + qd * 4;
            #pragma unroll
            for (int j = 0; j < 4; j++) {
                float4 v = *(const float4*)(wp + j * 16);
                int k = qd * 4 + j * 16;
                Wd[k][r]   = pack2(v.x, v.x);
                Wd[k+1][r] = pack2(v.y, v.y);
                Wd[k+2][r] = pack2(v.z, v.z);
                Wd[k+3][r] = pack2(v.w, v.w);
            }
        } else {
            #pragma unroll
            for (int j = 0; j < 4; j++) {
                int k = qd * 4 + j * 16;
                Wd[k][r] = 0; Wd[k+1][r] = 0; Wd[k+2][r] = 0; Wd[k+3][r] = 0;
            }
        }
    }
    __syncthreads();

    int tx = tid & 15, ty = tid >> 4;
    u64 acc[2][4] = {};
    #pragma unroll
    for (int k = 0; k < 64; k++) {
        double2 a2 = *(const double2*)&As[k][ty * 4];
        u64 a01 = __double_as_longlong(a2.x);
        u64 a23 = __double_as_longlong(a2.y);
        double2 w0 = *(const double2*)&Wd[k][tx * 4];
        double2 w1 = *(const double2*)&Wd[k][tx * 4 + 2];
        u64 b0 = __double_as_longlong(w0.x);
        u64 b1 = __double_as_longlong(w0.y);
        u64 b2 = __double_as_longlong(w1.x);
        u64 b3 = __double_as_longlong(w1.y);
        acc[0][0] = fma2(a01, b0, acc[0][0]);
        acc[0][1] = fma2(a01, b1, acc[0][1]);
        acc[0][2] = fma2(a01, b2, acc[0][2]);
        acc[0][3] = fma2(a01, b3, acc[0][3]);
        acc[1][0] = fma2(a23, b0, acc[1][0]);
        acc[1][1] = fma2(a23, b1, acc[1][1]);
        acc[1][2] = fma2(a23, b2, acc[1][2]);
        acc[1][3] = fma2(a23, b3, acc[1][3]);
    }

    float rv[4][4];
    #pragma unroll
    for (int v = 0; v < 4; v++) {
        unpack2(acc[0][v], rv[0][v], rv[1][v]);
        unpack2(acc[1][v], rv[2][v], rv[3][v]);
    }
    #pragma unroll
    for (int u = 0; u < 4; u++) {
        int row = rowBase + ty * 4 + u;
        #pragma unroll
        for (int v = 0; v < 4; v++) {
            int n = nBase + tx * 4 + v;
            if (n < N) {
                float val = rv[u][v] + bias[n];
                if (RELU) val = fmaxf(val, 0.0f);
                C[row * N + n] = val;
            }
        }
    }
}

// ============================================================================
// gemm64_ln: Y = LN(Y + A @ W^T + bias), N=K=64, fused epilogue.
// ============================================================================
__global__ __launch_bounds__(256) void gemm64_ln(
    const float* __restrict__ A, const float* __restrict__ W,
    const float* __restrict__ bias, float* __restrict__ Y,
    const float* __restrict__ gam, const float* __restrict__ bet)
{
    __shared__ __align__(16) float As[64][68];
    __shared__ __align__(16) u64  Wd[64][66];
    int tid = threadIdx.x;
    int rowBase = blockIdx.x * 64;

    int r = tid >> 2, qd = tid & 3;
    {
        const float* ap = A + (rowBase + r) * 64 + qd * 4;
        const float* wp = W + r * 64 + qd * 4;
        #pragma unroll
        for (int j = 0; j < 4; j++) {
            float4 va = *(const float4*)(ap + j * 16);
            float4 vw = *(const float4*)(wp + j * 16);
            int k = qd * 4 + j * 16;
            As[k][r] = va.x; As[k + 1][r] = va.y; As[k + 2][r] = va.z; As[k + 3][r] = va.w;
            Wd[k][r]   = pack2(vw.x, vw.x);
            Wd[k+1][r] = pack2(vw.y, vw.y);
            Wd[k+2][r] = pack2(vw.z, vw.z);
            Wd[k+3][r] = pack2(vw.w, vw.w);
        }
    }
    __syncthreads();

    int tx = tid & 15, ty = tid >> 4;
    u64 acc[2][4] = {};
    #pragma unroll
    for (int k = 0; k < 64; k++) {
        double2 a2 = *(const double2*)&As[k][ty * 4];
        u64 a01 = __double_as_longlong(a2.x);
        u64 a23 = __double_as_longlong(a2.y);
        double2 w0 = *(const double2*)&Wd[k][tx * 4];
        double2 w1 = *(const double2*)&Wd[k][tx * 4 + 2];
        u64 b0 = __double_as_longlong(w0.x);
        u64 b1 = __double_as_longlong(w0.y);
        u64 b2 = __double_as_longlong(w1.x);
        u64 b3 = __double_as_longlong(w1.y);
        acc[0][0] = fma2(a01, b0, acc[0][0]);
        acc[0][1] = fma2(a01, b1, acc[0][1]);
        acc[0][2] = fma2(a01, b2, acc[0][2]);
        acc[0][3] = fma2(a01, b3, acc[0][3]);
        acc[1][0] = fma2(a23, b0, acc[1][0]);
        acc[1][1] = fma2(a23, b1, acc[1][1]);
        acc[1][2] = fma2(a23, b2, acc[1][2]);
        acc[1][3] = fma2(a23, b3, acc[1][3]);
    }
    float rv[4][4];
    #pragma unroll
    for (int v = 0; v < 4; v++) {
        unpack2(acc[0][v], rv[0][v], rv[1][v]);
        unpack2(acc[1][v], rv[2][v], rv[3][v]);
    }
    __syncthreads();   // done reading As/Wd; reuse As as Z

    #pragma unroll
    for (int u = 0; u < 4; u++) {
        int row = ty * 4 + u;
        float4 yv = *(const float4*)&Y[(rowBase + row) * 64 + tx * 4];
        As[row][tx * 4 + 0] = rv[u][0] + bias[tx * 4 + 0] + yv.x;
        As[row][tx * 4 + 1] = rv[u][1] + bias[tx * 4 + 1] + yv.y;
        As[row][tx * 4 + 2] = rv[u][2] + bias[tx * 4 + 2] + yv.z;
        As[row][tx * 4 + 3] = rv[u][3] + bias[tx * 4 + 3] + yv.w;
    }
    __syncthreads();

    int wid = tid >> 5, lane = tid & 31;
    #pragma unroll 1
    for (int i = 0; i < 8; i++) {
        int row = wid * 8 + i;
        float z0 = As[row][lane];
        float z1 = As[row][lane + 32];
        float s = z0 + z1;
        float ss = z0 * z0 + z1 * z1;
        #pragma unroll
        for (int off = 16; off; off >>= 1) {
            s  += __shfl_xor_sync(0xFFFFFFFFu, s, off);
            ss += __shfl_xor_sync(0xFFFFFFFFu, ss, off);
        }
        float mean = s * (1.0f / 64.0f);
        float var = ss * (1.0f / 64.0f) - mean * mean;
        float inv = rsqrtf(var + EPSV);
        Y[(rowBase + row) * 64 + lane]      = (z0 - mean) * inv * gam[lane]      + bet[lane];
        Y[(rowBase + row) * 64 + 32 + lane] = (z1 - mean) * inv * gam[32 + lane] + bet[32 + lane];
    }
}

// ============================================================================
// gemm_sk: partial[z][M,64] = A[M,kchunk] @ W[64,kchunk]^T (deterministic, no atomics)
// ============================================================================
__global__ __launch_bounds__(256) void gemm_sk(
    const float* __restrict__ A, const float* __restrict__ W,
    float* __restrict__ Cpart, int K)
{
    __shared__ __align__(16) float As[64][68];
    __shared__ __align__(16) u64  Wd[64][66];
    int tid = threadIdx.x;
    int rowBase = blockIdx.y * 64;
    int kChunk = K / gridDim.z;
    int kStart = blockIdx.z * kChunk;
    float* Cp = Cpart + blockIdx.z * (BSR * 64);

    int r = tid >> 2, qd = tid & 3;
    int tx = tid & 15, ty = tid >> 4;
    u64 acc[2][4] = {};

    for (int k0 = kStart; k0 < kStart + kChunk; k0 += 64) {
        __syncthreads();
        const float* ap = A + (rowBase + r) * K + k0 + qd * 4;
        const float* wp = W + r * K + k0 + qd * 4;
        #pragma unroll
        for (int j = 0; j < 4; j++) {
            float4 va = *(const float4*)(ap + j * 16);
            float4 vw = *(const float4*)(wp + j * 16);
            int k = qd * 4 + j * 16;
            As[k][r] = va.x; As[k + 1][r] = va.y; As[k + 2][r] = va.z; As[k + 3][r] = va.w;
            Wd[k][r]   = pack2(vw.x, vw.x);
            Wd[k+1][r] = pack2(vw.y, vw.y);
            Wd[k+2][r] = pack2(vw.z, vw.z);
            Wd[k+3][r] = pack2(vw.w, vw.w);
        }
        __syncthreads();
        #pragma unroll
        for (int k = 0; k < 64; k++) {
            double2 a2 = *(const double2*)&As[k][ty * 4];
            u64 a01 = __double_as_longlong(a2.x);
            u64 a23 = __double_as_longlong(a2.y);
            double2 w0 = *(const double2*)&Wd[k][tx * 4];
            double2 w1 = *(const double2*)&Wd[k][tx * 4 + 2];
            u64 b0 = __double_as_longlong(w0.x);
            u64 b1 = __double_as_longlong(w0.y);
            u64 b2 = __double_as_longlong(w1.x);
            u64 b3 = __double_as_longlong(w1.y);
            acc[0][0] = fma2(a01, b0, acc[0][0]);
            acc[0][1] = fma2(a01, b1, acc[0][1]);
            acc[0][2] = fma2(a01, b2, acc[0][2]);
            acc[0][3] = fma2(a01, b3, acc[0][3]);
            acc[1][0] = fma2(a23, b0, acc[1][0]);
            acc[1][1] = fma2(a23, b1, acc[1][1]);
            acc[1][2] = fma2(a23, b2, acc[1][2]);
            acc[1][3] = fma2(a23, b3, acc[1][3]);
        }
    }

    float rv[4][4];
    #pragma unroll
    for (int v = 0; v < 4; v++) {
        unpack2(acc[0][v], rv[0][v], rv[1][v]);
        unpack2(acc[1][v], rv[2][v], rv[3][v]);
    }
    #pragma unroll
    for (int u = 0; u < 4; u++) {
        int row = rowBase + ty * 4 + u;
        *(float4*)&Cp[row * 64 + tx * 4] =
            make_float4(rv[u][0], rv[u][1], rv[u][2], rv[u][3]);
    }
}

// ---------------- merge split-K partials + bias + residual + LN ----------------
__global__ __launch_bounds__(256) void add_ln_ff(
    float* __restrict__ Y, const float* __restrict__ part,
    const float* __restrict__ bias,
    const float* __restrict__ gam, const float* __restrict__ bet)
{
    int row = blockIdx.x * 8 + (threadIdx.x >> 5);
    int lane = threadIdx.x & 31;
    float z0 = Y[row * 64 + lane]      + bias[lane];
    float z1 = Y[row * 64 + 32 + lane] + bias[32 + lane];
    #pragma unroll
    for (int z = 0; z < ZSPL; z++) {
        z0 += part[z * (BSR * 64) + row * 64 + lane];
        z1 += part[z * (BSR * 64) + row * 64 + 32 + lane];
    }
    float s = z0 + z1;
    float ss = z0 * z0 + z1 * z1;
    #pragma unroll
    for (int off = 16; off; off >>= 1) {
        s  += __shfl_xor_sync(0xFFFFFFFFu, s, off);
        ss += __shfl_xor_sync(0xFFFFFFFFu, ss, off);
    }
    float mean = s * (1.0f / 64.0f);
    float var = ss * (1.0f / 64.0f) - mean * mean;
    float inv = rsqrtf(var + EPSV);
    Y[row * 64 + lane]      = (z0 - mean) * inv * gam[lane]      + bet[lane];
    Y[row * 64 + 32 + lane] = (z1 - mean) * inv * gam[32 + lane] + bet[32 + lane];
}

// ---------------- attention: unshifted softmax (R8 version, unchanged) --------
// grid (B*NH, S/128), block 384. Group g (128 threads) handles 6 of 18 key tiles.
__global__ __launch_bounds__(384) void attention_kernel(
    const float* __restrict__ qkv, float* __restrict__ o)
{
    __shared__ __align__(16) float Kt[3][128][8];
    __shared__ __align__(16) float Vt[3][128][8];
    __shared__ float Ss[2][128];
    __shared__ float Accs[2][128][8];

    int tid = threadIdx.x;
    int g = tid >> 7;          // 0..2
    int t = tid & 127;
    int bh = blockIdx.x;
    int b = bh >> 3, h = bh & 7;
    int qbase = blockIdx.y * 128;
    int srow = b * SB + qbase + t;

    const float QS = 0.35355339059327373f * 1.4426950408889634f;
    const float* qp = qkv + srow * 192 + h * 8;
    float4 qa = *(const float4*)qp;
    float4 qb = *(const float4*)(qp + 4);
    u64 q01 = pack2(qa.x * QS, qa.y * QS);
    u64 q23 = pack2(qa.z * QS, qa.w * QS);
    u64 q45 = pack2(qb.x * QS, qb.y * QS);
    u64 q67 = pack2(qb.z * QS, qb.w * QS);

    float sum = 0.0f;
    u64 a01 = 0, a23 = 0, a45 = 0, a67 = 0;

    for (int tile = g; tile < 18; tile += 3) {
        int krow = b * SB + tile * 128 + t;
        const float* kp = qkv + krow * 192 + 64 + h * 8;
        float4 k0 = *(const float4*)kp;
        float4 k1 = *(const float4*)(kp + 4);
        float4 v0 = *(const float4*)(kp + 64);
        float4 v1 = *(const float4*)(kp + 68);
        *(float4*)&Kt[g][t][0] = k0; *(float4*)&Kt[g][t][4] = k1;
        *(float4*)&Vt[g][t][0] = v0; *(float4*)&Vt[g][t][4] = v1;
        asm volatile("bar.sync %0, 128;" :: "r"(g + 1) : "memory");

        #pragma unroll 4
        for (int kk = 0; kk < 128; kk++) {
            double2 ka = *(const double2*)&Kt[g][kk][0];
            double2 kb2 = *(const double2*)&Kt[g][kk][4];
            u64 d = mul2(q01, __double_as_longlong(ka.x));
            d = fma2(q23, __double_as_longlong(ka.y), d);
            d = fma2(q45, __double_as_longlong(kb2.x), d);
            d = fma2(q67, __double_as_longlong(kb2.y), d);
            float lo, hi;
            unpack2(d, lo, hi);
            float s = fminf(lo + hi, 80.0f);
            float e = ex2f(s);
            sum += e;
            u64 pe = pack2(e, e);
            double2 va = *(const double2*)&Vt[g][kk][0];
            double2 vb2 = *(const double2*)&Vt[g][kk][4];
            a01 = fma2(pe, __double_as_longlong(va.x), a01);
            a23 = fma2(pe, __double_as_longlong(va.y), a23);
            a45 = fma2(pe, __double_as_longlong(vb2.x), a45);
            a67 = fma2(pe, __double_as_longlong(vb2.y), a67);
        }
        asm volatile("bar.sync %0, 128;" :: "r"(g + 1) : "memory");
    }

    float av[8];
    unpack2(a01, av[0], av[1]);
    unpack2(a23, av[2], av[3]);
    unpack2(a45, av[4], av[5]);
    unpack2(a67, av[6], av[7]);

    if (g > 0) {
        Ss[g - 1][t] = sum;
        #pragma unroll
        for (int j = 0; j < 8; j++) Accs[g - 1][t][j] = av[j];
    }
    __syncthreads();
    if (g == 0) {
        sum += Ss[0][t] + Ss[1][t];
        #pragma unroll
        for (int j = 0; j < 8; j++)
            av[j] += Accs[0][t][j] + Accs[1][t][j];
        float inv = 1.0f / sum;
        float* op = o + srow * 64 + h * 8;
        float4 o0 = make_float4(av[0]*inv, av[1]*inv, av[2]*inv, av[3]*inv);
        float4 o1 = make_float4(av[4]*inv, av[5]*inv, av[6]*inv, av[7]*inv);
        *(float4*)op = o0;
        *(float4*)(op + 4) = o1;
    }
}

// ---------------- final softmax over 441 + transpose to [B,441,S] ----------
__global__ __launch_bounds__(128) void softmax_t_kernel(
    const float* __restrict__ sc, float* __restrict__ outK)
{
    __shared__ float red[128];
    int row = blockIdx.x;
    int b = row / SB, s = row % SB;
    int tid = threadIdx.x;
    float v[4];
    float mx = -1e30f;
    #pragma unroll
    for (int i = 0; i < 4; i++) {
        int p = tid + i * 128;
        v[i] = (p < KK2) ? sc[row * KK2 + p] : -1e30f;
        mx = fmaxf(mx, v[i]);
    }
    red[tid] = mx; __syncthreads();
    for (int o = 64; o; o >>= 1) { if (tid < o) red[tid] = fmaxf(red[tid], red[tid + o]); __syncthreads(); }
    float m = red[0]; __syncthreads();
    float sum = 0.0f;
    #pragma unroll
    for (int i = 0; i < 4; i++) {
        int p = tid + i * 128;
        v[i] = (p < KK2) ? __expf(v[i] - m) : 0.0f;
        sum += v[i];
    }
    red[tid] = sum; __syncthreads();
    for (int o = 64; o; o >>= 1) { if (tid < o) red[tid] += red[tid + o]; __syncthreads(); }
    float inv = 1.0f / red[0];
    #pragma unroll
    for (int i = 0; i < 4; i++) {
        int p = tid + i * 128;
        if (p < KK2) outK[(b * KK2 + p) * SB + s] = v[i] * inv;
    }
}

// ---------------- apply predicted kernel (reflect pad) ----------------
__global__ __launch_bounds__(256) void apply_kernel(
    const float* __restrict__ x, const float* __restrict__ kern, float* __restrict__ out)
{
    int idx = blockIdx.x * 256 + threadIdx.x;
    if (idx >= BB * CC * HH * WWD) return;
    int ww = idx % WWD;
    int hh = (idx / WWD) % HH;
    int c = (idx / (HH * WWD)) % CC;
    int b = idx / (CC * HH * WWD);
    const float* kb = kern + b * KK2 * SB + hh * WWD + ww;
    const float* xb = x + (b * CC + c) * HH * WWD;
    float acc = 0.0f;
    #pragma unroll 1
    for (int kh = 0; kh < KS; kh++) {
        int ih = hh + kh - 10;
        if (ih < 0) ih = -ih;
        else if (ih >= HH) ih = 2 * HH - 2 - ih;
        const float* xr = xb + ih * WWD;
        #pragma unroll
        for (int kw = 0; kw < KS; kw++) {
            int iw = ww + kw - 10;
            if (iw < 0) iw = -iw;
            else if (iw >= WWD) iw = 2 * WWD - 2 - iw;
            acc = fmaf(xr[iw], kb[(kh * KS + kw) * SB], acc);
        }
    }
    out[idx] = acc;
}

// ---------------- host launcher ----------------
extern "C" void kernel_launch(void* const* d_in, const int* in_sizes, int n_in,
                              void* d_out, int out_size)
{
    const float* x        = (const float*)d_in[0];
    const float* conv1_w  = (const float*)d_in[1];
    const float* conv1_b  = (const float*)d_in[2];
    const float* bn_gamma = (const float*)d_in[3];
    const float* bn_beta  = (const float*)d_in[4];
    const float* bn_mean  = (const float*)d_in[5];
    const float* bn_var   = (const float*)d_in[6];
    const float* attn_in_w  = (const float*)d_in[7];
    const float* attn_in_b  = (const float*)d_in[8];
    const float* attn_out_w = (const float*)d_in[9];
    const float* attn_out_b = (const float*)d_in[10];
    const float* lin1_w   = (const float*)d_in[11];
    const float* lin1_b   = (const float*)d_in[12];
    const float* lin2_w   = (const float*)d_in[13];
    const float* lin2_b   = (const float*)d_in[14];
    const float* ln1_g    = (const float*)d_in[15];
    const float* ln1_b    = (const float*)d_in[16];
    const float* ln2_g    = (const float*)d_in[17];
    const float* ln2_b    = (const float*)d_in[18];
    const float* last_w   = (const float*)d_in[19];
    const float* last_b   = (const float*)d_in[20];

    float* out = (float*)d_out;
    float* kern = out + BB * CC * HH * WWD;

    float *py, *pqkv, *pattno, *ppart, *pff;
    cudaGetSymbolAddress((void**)&py, g_y);
    cudaGetSymbolAddress((void**)&pqkv, g_qkv);
    cudaGetSymbolAddress((void**)&pattno, g_attno);
    cudaGetSymbolAddress((void**)&ppart, g_part);
    cudaGetSymbolAddress((void**)&pff, g_ff);

    conv_bn_relu<<<(BSR * DD + 255) / 256, 256>>>(x, conv1_w, conv1_b, bn_gamma,
                                                  bn_beta, bn_mean, bn_var, py);

    for (int l = 0; l < NLAYER; l++) {
        // qkv = y @ Win^T + b   [4608,192]
        gemm64<0><<<dim3(3, BSR / 64), 256>>>(
            py, attn_in_w + l * 192 * DD, attn_in_b + l * 192, pqkv, 192);
        // attention -> attno [4608,64]
        attention_kernel<<<dim3(BB * NHH, SB / 128), 384>>>(pqkv, pattno);
        // y = LN(y + attno @ Wout^T + b)   (fused)
        gemm64_ln<<<BSR / 64, 256>>>(
            pattno, attn_out_w + l * DD * DD, attn_out_b + l * DD, py,
            ln1_g + l * DD, ln1_b + l * DD);
        // ff1 = relu(y @ W1^T + b1)  [4608,2048]
        gemm64<1><<<dim3(FFD / 64, BSR / 64), 256>>>(
            py, lin1_w + l * FFD * DD, lin1_b + l * FFD, pff, FFD);
        // ff2 partials: ff1 @ W2^T  [ZSPL][4608,64]
        gemm_sk<<<dim3(1, BSR / 64, ZSPL), 256>>>(pff, lin2_w + l * DD * FFD, ppart, FFD);
        // y = LN(y + sum(partials) + b2)
        add_ln_ff<<<BSR / 8, 256>>>(py, ppart, lin2_b + l * DD,
                                    ln2_g + l * DD, ln2_b + l * DD);
    }

    // scores = y @ last_w^T + last_b  [4608,441]
    gemm64<0><<<dim3((KK2 + 63) / 64, BSR / 64), 256>>>(py, last_w, last_b, pff, KK2);
    softmax_t_kernel<<<BSR, 128>>>(pff, kern);
    apply_kernel<<<(BB * CC * HH * WWD + 255) / 256, 256>>>(x, kern, out);
}

// round 13
// speedup vs baseline: 1.5599x; 1.5599x over previous
#include <cuda_runtime.h>

// ---------------- problem constants ----------------
#define SB    2304          // S = H*W
#define BSR   4608          // B*S
#define DD    64
#define NHH   8
#define FFD   2048
#define NLAYER 8
#define KS    21
#define KK2   441
#define HH    48
#define WWD   48
#define CC    3
#define BB    2
#define EPSV  1e-5f
#define ZSPL  8

typedef unsigned long long u64;

// ---------------- scratch ----------------
__device__ float g_y[BSR * DD];
__device__ float g_qkv[BSR * 3 * DD];
__device__ float g_attno[BSR * DD];
__device__ float g_part[ZSPL * BSR * DD];
__device__ float g_ff[BSR * FFD];

// ---------------- packed f32x2 helpers ----------------
__device__ __forceinline__ u64 fma2(u64 a, u64 b, u64 c) {
    u64 d;
    asm("fma.rn.f32x2 %0, %1, %2, %3;" : "=l"(d) : "l"(a), "l"(b), "l"(c));
    return d;
}
__device__ __forceinline__ u64 mul2(u64 a, u64 b) {
    u64 d;
    asm("mul.rn.f32x2 %0, %1, %2;" : "=l"(d) : "l"(a), "l"(b));
    return d;
}
__device__ __forceinline__ u64 pack2(float lo, float hi) {
    u64 d;
    asm("mov.b64 %0, {%1, %2};" : "=l"(d) : "r"(__float_as_uint(lo)), "r"(__float_as_uint(hi)));
    return d;
}
__device__ __forceinline__ void unpack2(u64 v, float& lo, float& hi) {
    unsigned a, b;
    asm("mov.b64 {%0, %1}, %2;" : "=r"(a), "=r"(b) : "l"(v));
    lo = __uint_as_float(a); hi = __uint_as_float(b);
}
__device__ __forceinline__ float ex2f(float x) {
    float r;
    asm("ex2.approx.f32 %0, %1;" : "=f"(r) : "f"(x));
    return r;
}

// ---------------- conv 3x3 + BN + ReLU -> [B,S,D] ----------------
__global__ __launch_bounds__(256) void conv_bn_relu(
    const float* __restrict__ x, const float* __restrict__ w,
    const float* __restrict__ cb, const float* __restrict__ gma,
    const float* __restrict__ bta, const float* __restrict__ mean,
    const float* __restrict__ var, float* __restrict__ y)
{
    int idx = blockIdx.x * 256 + threadIdx.x;
    if (idx >= BSR * DD) return;
    int d = idx & 63;
    int s = (idx >> 6) % SB;
    int b = idx / (SB * DD);
    int hh = s / WWD, ww = s % WWD;
    float sum = cb[d];
    #pragma unroll
    for (int ci = 0; ci < 3; ci++) {
        #pragma unroll
        for (int kh = 0; kh < 3; kh++) {
            int ih = hh + kh - 1;
            if ((unsigned)ih >= HH) continue;
            #pragma unroll
            for (int kw = 0; kw < 3; kw++) {
                int iw = ww + kw - 1;
                if ((unsigned)iw >= WWD) continue;
                sum += x[((b * CC + ci) * HH + ih) * WWD + iw] *
                       w[((d * CC + ci) * 3 + kh) * 3 + kw];
            }
        }
    }
    sum = (sum - mean[d]) * rsqrtf(var[d] + EPSV) * gma[d] + bta[d];
    y[idx] = fmaxf(sum, 0.0f);
}

// ---------------- gemm64: C[M,N] = A[M,64] @ W[N,64]^T + bias (R8 version) ----
// 64x64 tile, 256 threads, 4x4 per-thread register tile, FFMA2.
template<int RELU>
__global__ __launch_bounds__(256) void gemm64(
    const float* __restrict__ A, const float* __restrict__ W,
    const float* __restrict__ bias, float* __restrict__ C, int N)
{
    __shared__ __align__(16) float As[64][68];
    __shared__ __align__(16) float Ws[64][68];
    int tid = threadIdx.x;
    int rowBase = blockIdx.y * 64;
    int nBase = blockIdx.x * 64;

    int r = tid >> 2, qd = tid & 3;
    {
        const float* ap = A + (rowBase + r) * 64 + qd * 4;
        #pragma unroll
        for (int j = 0; j < 4; j++) {
            float4 v = *(const float4*)(ap + j * 16);
            int k = qd * 4 + j * 16;
            As[k][r] = v.x; As[k + 1][r] = v.y; As[k + 2][r] = v.z; As[k + 3][r] = v.w;
        }
        int n = nBase + r;
        if (n < N) {
            const float* wp = W + n * 64 + qd * 4;
            #pragma unroll
            for (int j = 0; j < 4; j++) {
                float4 v = *(const float4*)(wp + j * 16);
                int k = qd * 4 + j * 16;
                Ws[k][r] = v.x; Ws[k + 1][r] = v.y; Ws[k + 2][r] = v.z; Ws[k + 3][r] = v.w;
            }
        } else {
            #pragma unroll
            for (int j = 0; j < 4; j++) {
                int k = qd * 4 + j * 16;
                Ws[k][r] = 0.f; Ws[k + 1][r] = 0.f; Ws[k + 2][r] = 0.f; Ws[k + 3][r] = 0.f;
            }
        }
    }
    __syncthreads();

    int tx = tid & 15, ty = tid >> 4;
    u64 acc[2][4] = {};
    #pragma unroll
    for (int k = 0; k < 64; k++) {
        double2 a2 = *(const double2*)&As[k][ty * 4];
        u64 a01 = __double_as_longlong(a2.x);
        u64 a23 = __double_as_longlong(a2.y);
        float4 b4 = *(const float4*)&Ws[k][tx * 4];
        u64 b0 = pack2(b4.x, b4.x);
        u64 b1 = pack2(b4.y, b4.y);
        u64 b2 = pack2(b4.z, b4.z);
        u64 b3 = pack2(b4.w, b4.w);
        acc[0][0] = fma2(a01, b0, acc[0][0]);
        acc[0][1] = fma2(a01, b1, acc[0][1]);
        acc[0][2] = fma2(a01, b2, acc[0][2]);
        acc[0][3] = fma2(a01, b3, acc[0][3]);
        acc[1][0] = fma2(a23, b0, acc[1][0]);
        acc[1][1] = fma2(a23, b1, acc[1][1]);
        acc[1][2] = fma2(a23, b2, acc[1][2]);
        acc[1][3] = fma2(a23, b3, acc[1][3]);
    }

    float rv[4][4];
    #pragma unroll
    for (int v = 0; v < 4; v++) {
        unpack2(acc[0][v], rv[0][v], rv[1][v]);
        unpack2(acc[1][v], rv[2][v], rv[3][v]);
    }
    #pragma unroll
    for (int u = 0; u < 4; u++) {
        int row = rowBase + ty * 4 + u;
        #pragma unroll
        for (int v = 0; v < 4; v++) {
            int n = nBase + tx * 4 + v;
            if (n < N) {
                float val = rv[u][v] + bias[n];
                if (RELU) val = fmaxf(val, 0.0f);
                C[row * N + n] = val;
            }
        }
    }
}

// ---------------- gemm64_ln: Y = LN(Y + A @ W^T + bias), N=64, fused (R8) ------
__global__ __launch_bounds__(256) void gemm64_ln(
    const float* __restrict__ A, const float* __restrict__ W,
    const float* __restrict__ bias, float* __restrict__ Y,
    const float* __restrict__ gam, const float* __restrict__ bet)
{
    __shared__ __align__(16) float As[64][68];
    __shared__ __align__(16) float Ws[64][68];
    int tid = threadIdx.x;
    int rowBase = blockIdx.x * 64;

    int r = tid >> 2, qd = tid & 3;
    {
        const float* ap = A + (rowBase + r) * 64 + qd * 4;
        const float* wp = W + r * 64 + qd * 4;
        #pragma unroll
        for (int j = 0; j < 4; j++) {
            float4 va = *(const float4*)(ap + j * 16);
            float4 vw = *(const float4*)(wp + j * 16);
            int k = qd * 4 + j * 16;
            As[k][r] = va.x; As[k + 1][r] = va.y; As[k + 2][r] = va.z; As[k + 3][r] = va.w;
            Ws[k][r] = vw.x; Ws[k + 1][r] = vw.y; Ws[k + 2][r] = vw.z; Ws[k + 3][r] = vw.w;
        }
    }
    __syncthreads();

    int tx = tid & 15, ty = tid >> 4;
    u64 acc[2][4] = {};
    #pragma unroll
    for (int k = 0; k < 64; k++) {
        double2 a2 = *(const double2*)&As[k][ty * 4];
        u64 a01 = __double_as_longlong(a2.x);
        u64 a23 = __double_as_longlong(a2.y);
        float4 b4 = *(const float4*)&Ws[k][tx * 4];
        u64 b0 = pack2(b4.x, b4.x);
        u64 b1 = pack2(b4.y, b4.y);
        u64 b2 = pack2(b4.z, b4.z);
        u64 b3 = pack2(b4.w, b4.w);
        acc[0][0] = fma2(a01, b0, acc[0][0]);
        acc[0][1] = fma2(a01, b1, acc[0][1]);
        acc[0][2] = fma2(a01, b2, acc[0][2]);
        acc[0][3] = fma2(a01, b3, acc[0][3]);
        acc[1][0] = fma2(a23, b0, acc[1][0]);
        acc[1][1] = fma2(a23, b1, acc[1][1]);
        acc[1][2] = fma2(a23, b2, acc[1][2]);
        acc[1][3] = fma2(a23, b3, acc[1][3]);
    }
    float rv[4][4];
    #pragma unroll
    for (int v = 0; v < 4; v++) {
        unpack2(acc[0][v], rv[0][v], rv[1][v]);
        unpack2(acc[1][v], rv[2][v], rv[3][v]);
    }
    __syncthreads();   // done reading Ws; reuse as Z

    #pragma unroll
    for (int u = 0; u < 4; u++) {
        int row = ty * 4 + u;
        float4 yv = *(const float4*)&Y[(rowBase + row) * 64 + tx * 4];
        Ws[row][tx * 4 + 0] = rv[u][0] + bias[tx * 4 + 0] + yv.x;
        Ws[row][tx * 4 + 1] = rv[u][1] + bias[tx * 4 + 1] + yv.y;
        Ws[row][tx * 4 + 2] = rv[u][2] + bias[tx * 4 + 2] + yv.z;
        Ws[row][tx * 4 + 3] = rv[u][3] + bias[tx * 4 + 3] + yv.w;
    }
    __syncthreads();

    int wid = tid >> 5, lane = tid & 31;
    #pragma unroll 1
    for (int i = 0; i < 8; i++) {
        int row = wid * 8 + i;
        float z0 = Ws[row][lane];
        float z1 = Ws[row][lane + 32];
        float s = z0 + z1;
        float ss = z0 * z0 + z1 * z1;
        #pragma unroll
        for (int off = 16; off; off >>= 1) {
            s  += __shfl_xor_sync(0xFFFFFFFFu, s, off);
            ss += __shfl_xor_sync(0xFFFFFFFFu, ss, off);
        }
        float mean = s * (1.0f / 64.0f);
        float var = ss * (1.0f / 64.0f) - mean * mean;
        float inv = rsqrtf(var + EPSV);
        Y[(rowBase + row) * 64 + lane]      = (z0 - mean) * inv * gam[lane]      + bet[lane];
        Y[(rowBase + row) * 64 + 32 + lane] = (z1 - mean) * inv * gam[32 + lane] + bet[32 + lane];
    }
}

// ---------------- lin2 split-K GEMM: deterministic partials (R8 loop) ---------
__global__ __launch_bounds__(256) void gemm_sk(
    const float* __restrict__ A, const float* __restrict__ W,
    float* __restrict__ Cpart, int K)
{
    __shared__ __align__(16) float As[64][68];
    __shared__ __align__(16) float Ws[64][68];
    int tid = threadIdx.x;
    int rowBase = blockIdx.y * 64;
    int kChunk = K / gridDim.z;
    int kStart = blockIdx.z * kChunk;
    float* Cp = Cpart + blockIdx.z * (BSR * 64);
    int r = tid >> 2, qd = tid & 3;
    int tx = tid & 15, ty = tid >> 4;

    u64 acc[2][4] = {};
    for (int k0 = kStart; k0 < kStart + kChunk; k0 += 64) {
        __syncthreads();
        const float* ap = A + (rowBase + r) * K + k0 + qd * 4;
        const float* wp = W + r * K + k0 + qd * 4;
        #pragma unroll
        for (int j = 0; j < 4; j++) {
            float4 va = *(const float4*)(ap + j * 16);
            float4 vw = *(const float4*)(wp + j * 16);
            int k = qd * 4 + j * 16;
            As[k][r] = va.x; As[k + 1][r] = va.y; As[k + 2][r] = va.z; As[k + 3][r] = va.w;
            Ws[k][r] = vw.x; Ws[k + 1][r] = vw.y; Ws[k + 2][r] = vw.z; Ws[k + 3][r] = vw.w;
        }
        __syncthreads();
        #pragma unroll
        for (int k = 0; k < 64; k++) {
            double2 a2 = *(const double2*)&As[k][ty * 4];
            u64 a01 = __double_as_longlong(a2.x);
            u64 a23 = __double_as_longlong(a2.y);
            float4 b4 = *(const float4*)&Ws[k][tx * 4];
            u64 b0 = pack2(b4.x, b4.x);
            u64 b1 = pack2(b4.y, b4.y);
            u64 b2 = pack2(b4.z, b4.z);
            u64 b3 = pack2(b4.w, b4.w);
            acc[0][0] = fma2(a01, b0, acc[0][0]);
            acc[0][1] = fma2(a01, b1, acc[0][1]);
            acc[0][2] = fma2(a01, b2, acc[0][2]);
            acc[0][3] = fma2(a01, b3, acc[0][3]);
            acc[1][0] = fma2(a23, b0, acc[1][0]);
            acc[1][1] = fma2(a23, b1, acc[1][1]);
            acc[1][2] = fma2(a23, b2, acc[1][2]);
            acc[1][3] = fma2(a23, b3, acc[1][3]);
        }
    }

    float rv[4][4];
    #pragma unroll
    for (int v = 0; v < 4; v++) {
        unpack2(acc[0][v], rv[0][v], rv[1][v]);
        unpack2(acc[1][v], rv[2][v], rv[3][v]);
    }
    #pragma unroll
    for (int u = 0; u < 4; u++) {
        int row = rowBase + ty * 4 + u;
        *(float4*)&Cp[row * 64 + tx * 4] =
            make_float4(rv[u][0], rv[u][1], rv[u][2], rv[u][3]);
    }
}

// ---------------- merge split-K partials + bias + residual + LN ----------------
__global__ __launch_bounds__(256) void add_ln_ff(
    float* __restrict__ Y, const float* __restrict__ part,
    const float* __restrict__ bias,
    const float* __restrict__ gam, const float* __restrict__ bet)
{
    int row = blockIdx.x * 8 + (threadIdx.x >> 5);
    int lane = threadIdx.x & 31;
    float z0 = Y[row * 64 + lane]      + bias[lane];
    float z1 = Y[row * 64 + 32 + lane] + bias[32 + lane];
    #pragma unroll
    for (int z = 0; z < ZSPL; z++) {
        z0 += part[z * (BSR * 64) + row * 64 + lane];
        z1 += part[z * (BSR * 64) + row * 64 + 32 + lane];
    }
    float s = z0 + z1;
    float ss = z0 * z0 + z1 * z1;
    #pragma unroll
    for (int off = 16; off; off >>= 1) {
        s  += __shfl_xor_sync(0xFFFFFFFFu, s, off);
        ss += __shfl_xor_sync(0xFFFFFFFFu, ss, off);
    }
    float mean = s * (1.0f / 64.0f);
    float var = ss * (1.0f / 64.0f) - mean * mean;
    float inv = rsqrtf(var + EPSV);
    Y[row * 64 + lane]      = (z0 - mean) * inv * gam[lane]      + bet[lane];
    Y[row * 64 + 32 + lane] = (z1 - mean) * inv * gam[32 + lane] + bet[32 + lane];
}

// ---------------- attention: unshifted softmax (R8, clamp removed) ------------
// grid (B*NH, S/128), block 384. Group g (128 threads) handles 6 of 18 key tiles.
__global__ __launch_bounds__(384) void attention_kernel(
    const float* __restrict__ qkv, float* __restrict__ o)
{
    __shared__ __align__(16) float Kt[3][128][8];
    __shared__ __align__(16) float Vt[3][128][8];
    __shared__ float Ss[2][128];
    __shared__ float Accs[2][128][8];

    int tid = threadIdx.x;
    int g = tid >> 7;          // 0..2
    int t = tid & 127;
    int bh = blockIdx.x;
    int b = bh >> 3, h = bh & 7;
    int qbase = blockIdx.y * 128;
    int srow = b * SB + qbase + t;

    const float QS = 0.35355339059327373f * 1.4426950408889634f;
    const float* qp = qkv + srow * 192 + h * 8;
    float4 qa = *(const float4*)qp;
    float4 qb = *(const float4*)(qp + 4);
    u64 q01 = pack2(qa.x * QS, qa.y * QS);
    u64 q23 = pack2(qa.z * QS, qa.w * QS);
    u64 q45 = pack2(qb.x * QS, qb.y * QS);
    u64 q67 = pack2(qb.z * QS, qb.w * QS);

    float sum = 0.0f;
    u64 a01 = 0, a23 = 0, a45 = 0, a67 = 0;

    for (int tile = g; tile < 18; tile += 3) {
        int krow = b * SB + tile * 128 + t;
        const float* kp = qkv + krow * 192 + 64 + h * 8;
        float4 k0 = *(const float4*)kp;
        float4 k1 = *(const float4*)(kp + 4);
        float4 v0 = *(const float4*)(kp + 64);
        float4 v1 = *(const float4*)(kp + 68);
        *(float4*)&Kt[g][t][0] = k0; *(float4*)&Kt[g][t][4] = k1;
        *(float4*)&Vt[g][t][0] = v0; *(float4*)&Vt[g][t][4] = v1;
        asm volatile("bar.sync %0, 128;" :: "r"(g + 1) : "memory");

        #pragma unroll 4
        for (int kk = 0; kk < 128; kk++) {
            double2 ka = *(const double2*)&Kt[g][kk][0];
            double2 kb2 = *(const double2*)&Kt[g][kk][4];
            u64 d = mul2(q01, __double_as_longlong(ka.x));
            d = fma2(q23, __double_as_longlong(ka.y), d);
            d = fma2(q45, __double_as_longlong(kb2.x), d);
            d = fma2(q67, __double_as_longlong(kb2.y), d);
            float lo, hi;
            unpack2(d, lo, hi);
            float e = ex2f(lo + hi);
            sum += e;
            u64 pe = pack2(e, e);
            double2 va = *(const double2*)&Vt[g][kk][0];
            double2 vb2 = *(const double2*)&Vt[g][kk][4];
            a01 = fma2(pe, __double_as_longlong(va.x), a01);
            a23 = fma2(pe, __double_as_longlong(va.y), a23);
            a45 = fma2(pe, __double_as_longlong(vb2.x), a45);
            a67 = fma2(pe, __double_as_longlong(vb2.y), a67);
        }
        asm volatile("bar.sync %0, 128;" :: "r"(g + 1) : "memory");
    }

    float av[8];
    unpack2(a01, av[0], av[1]);
    unpack2(a23, av[2], av[3]);
    unpack2(a45, av[4], av[5]);
    unpack2(a67, av[6], av[7]);

    if (g > 0) {
        Ss[g - 1][t] = sum;
        #pragma unroll
        for (int j = 0; j < 8; j++) Accs[g - 1][t][j] = av[j];
    }
    __syncthreads();
    if (g == 0) {
        sum += Ss[0][t] + Ss[1][t];
        #pragma unroll
        for (int j = 0; j < 8; j++)
            av[j] += Accs[0][t][j] + Accs[1][t][j];
        float inv = 1.0f / sum;
        float* op = o + srow * 64 + h * 8;
        float4 o0 = make_float4(av[0]*inv, av[1]*inv, av[2]*inv, av[3]*inv);
        float4 o1 = make_float4(av[4]*inv, av[5]*inv, av[6]*inv, av[7]*inv);
        *(float4*)op = o0;
        *(float4*)(op + 4) = o1;
    }
}

// ---------------- final softmax over 441 + transpose to [B,441,S] ----------
__global__ __launch_bounds__(128) void softmax_t_kernel(
    const float* __restrict__ sc, float* __restrict__ outK)
{
    __shared__ float red[128];
    int row = blockIdx.x;
    int b = row / SB, s = row % SB;
    int tid = threadIdx.x;
    float v[4];
    float mx = -1e30f;
    #pragma unroll
    for (int i = 0; i < 4; i++) {
        int p = tid + i * 128;
        v[i] = (p < KK2) ? sc[row * KK2 + p] : -1e30f;
        mx = fmaxf(mx, v[i]);
    }
    red[tid] = mx; __syncthreads();
    for (int o = 64; o; o >>= 1) { if (tid < o) red[tid] = fmaxf(red[tid], red[tid + o]); __syncthreads(); }
    float m = red[0]; __syncthreads();
    float sum = 0.0f;
    #pragma unroll
    for (int i = 0; i < 4; i++) {
        int p = tid + i * 128;
        v[i] = (p < KK2) ? __expf(v[i] - m) : 0.0f;
        sum += v[i];
    }
    red[tid] = sum; __syncthreads();
    for (int o = 64; o; o >>= 1) { if (tid < o) red[tid] += red[tid + o]; __syncthreads(); }
    float inv = 1.0f / red[0];
    #pragma unroll
    for (int i = 0; i < 4; i++) {
        int p = tid + i * 128;
        if (p < KK2) outK[(b * KK2 + p) * SB + s] = v[i] * inv;
    }
}

// ---------------- apply predicted kernel (reflect pad), 128-thr blocks --------
__global__ __launch_bounds__(128) void apply_kernel(
    const float* __restrict__ x, const float* __restrict__ kern, float* __restrict__ out)
{
    int idx = blockIdx.x * 128 + threadIdx.x;
    if (idx >= BB * CC * HH * WWD) return;
    int ww = idx % WWD;
    int hh = (idx / WWD) % HH;
    int c = (idx / (HH * WWD)) % CC;
    int b = idx / (CC * HH * WWD);
    const float* kb = kern + b * KK2 * SB + hh * WWD + ww;
    const float* xb = x + (b * CC + c) * HH * WWD;
    float acc = 0.0f;
    #pragma unroll 1
    for (int kh = 0; kh < KS; kh++) {
        int ih = hh + kh - 10;
        if (ih < 0) ih = -ih;
        else if (ih >= HH) ih = 2 * HH - 2 - ih;
        const float* xr = xb + ih * WWD;
        #pragma unroll
        for (int kw = 0; kw < KS; kw++) {
            int iw = ww + kw - 10;
            if (iw < 0) iw = -iw;
            else if (iw >= WWD) iw = 2 * WWD - 2 - iw;
            acc = fmaf(xr[iw], kb[(kh * KS + kw) * SB], acc);
        }
    }
    out[idx] = acc;
}

// ---------------- host launcher ----------------
extern "C" void kernel_launch(void* const* d_in, const int* in_sizes, int n_in,
                              void* d_out, int out_size)
{
    const float* x        = (const float*)d_in[0];
    const float* conv1_w  = (const float*)d_in[1];
    const float* conv1_b  = (const float*)d_in[2];
    const float* bn_gamma = (const float*)d_in[3];
    const float* bn_beta  = (const float*)d_in[4];
    const float* bn_mean  = (const float*)d_in[5];
    const float* bn_var   = (const float*)d_in[6];
    const float* attn_in_w  = (const float*)d_in[7];
    const float* attn_in_b  = (const float*)d_in[8];
    const float* attn_out_w = (const float*)d_in[9];
    const float* attn_out_b = (const float*)d_in[10];
    const float* lin1_w   = (const float*)d_in[11];
    const float* lin1_b   = (const float*)d_in[12];
    const float* lin2_w   = (const float*)d_in[13];
    const float* lin2_b   = (const float*)d_in[14];
    const float* ln1_g    = (const float*)d_in[15];
    const float* ln1_b    = (const float*)d_in[16];
    const float* ln2_g    = (const float*)d_in[17];
    const float* ln2_b    = (const float*)d_in[18];
    const float* last_w   = (const float*)d_in[19];
    const float* last_b   = (const float*)d_in[20];

    float* out = (float*)d_out;
    float* kern = out + BB * CC * HH * WWD;

    float *py, *pqkv, *pattno, *ppart, *pff;
    cudaGetSymbolAddress((void**)&py, g_y);
    cudaGetSymbolAddress((void**)&pqkv, g_qkv);
    cudaGetSymbolAddress((void**)&pattno, g_attno);
    cudaGetSymbolAddress((void**)&ppart, g_part);
    cudaGetSymbolAddress((void**)&pff, g_ff);

    conv_bn_relu<<<(BSR * DD + 255) / 256, 256>>>(x, conv1_w, conv1_b, bn_gamma,
                                                  bn_beta, bn_mean, bn_var, py);

    for (int l = 0; l < NLAYER; l++) {
        // qkv = y @ Win^T + b   [4608,192]
        gemm64<0><<<dim3(3, BSR / 64), 256>>>(
            py, attn_in_w + l * 192 * DD, attn_in_b + l * 192, pqkv, 192);
        // attention -> attno [4608,64]
        attention_kernel<<<dim3(BB * NHH, SB / 128), 384>>>(pqkv, pattno);
        // y = LN(y + attno @ Wout^T + b)   (fused)
        gemm64_ln<<<BSR / 64, 256>>>(
            pattno, attn_out_w + l * DD * DD, attn_out_b + l * DD, py,
            ln1_g + l * DD, ln1_b + l * DD);
        // ff1 = relu(y @ W1^T + b1)  [4608,2048]
        gemm64<1><<<dim3(FFD / 64, BSR / 64), 256>>>(
            py, lin1_w + l * FFD * DD, lin1_b + l * FFD, pff, FFD);
        // ff2 partials: ff1 @ W2^T  [ZSPL][4608,64] (deterministic, no atomics)
        gemm_sk<<<dim3(1, BSR / 64, ZSPL), 256>>>(pff, lin2_w + l * DD * FFD, ppart, FFD);
        // y = LN(y + sum(partials) + b2)
        add_ln_ff<<<BSR / 8, 256>>>(py, ppart, lin2_b + l * DD,
                                    ln2_g + l * DD, ln2_b + l * DD);
    }

    // scores = y @ last_w^T + last_b  [4608,441]
    gemm64<0><<<dim3((KK2 + 63) / 64, BSR / 64), 256>>>(py, last_w, last_b, pff, KK2);
    softmax_t_kernel<<<BSR, 128>>>(pff, kern);
    apply_kernel<<<(BB * CC * HH * WWD + 127) / 128, 128>>>(x, kern, out);
}

// round 14
// speedup vs baseline: 1.6703x; 1.0708x over previous
#include <cuda_runtime.h>

// ---------------- problem constants ----------------
#define SB    2304          // S = H*W
#define BSR   4608          // B*S
#define DD    64
#define NHH   8
#define FFD   2048
#define NLAYER 8
#define KS    21
#define KK2   441
#define HH    48
#define WWD   48
#define CC    3
#define BB    2
#define EPSV  1e-5f
#define ZSPL  8

typedef unsigned long long u64;

// ---------------- scratch ----------------
__device__ float g_y[BSR * DD];
__device__ float g_qkv[BSR * 3 * DD];
__device__ float g_attno[BSR * DD];
__device__ float g_part[ZSPL * BSR * DD];
__device__ float g_ff[BSR * FFD];    // used only for final scores now

// ---------------- packed f32x2 helpers ----------------
__device__ __forceinline__ u64 fma2(u64 a, u64 b, u64 c) {
    u64 d;
    asm("fma.rn.f32x2 %0, %1, %2, %3;" : "=l"(d) : "l"(a), "l"(b), "l"(c));
    return d;
}
__device__ __forceinline__ u64 mul2(u64 a, u64 b) {
    u64 d;
    asm("mul.rn.f32x2 %0, %1, %2;" : "=l"(d) : "l"(a), "l"(b));
    return d;
}
__device__ __forceinline__ u64 pack2(float lo, float hi) {
    u64 d;
    asm("mov.b64 %0, {%1, %2};" : "=l"(d) : "r"(__float_as_uint(lo)), "r"(__float_as_uint(hi)));
    return d;
}
__device__ __forceinline__ void unpack2(u64 v, float& lo, float& hi) {
    unsigned a, b;
    asm("mov.b64 {%0, %1}, %2;" : "=r"(a), "=r"(b) : "l"(v));
    lo = __uint_as_float(a); hi = __uint_as_float(b);
}
__device__ __forceinline__ float ex2f(float x) {
    float r;
    asm("ex2.approx.f32 %0, %1;" : "=f"(r) : "f"(x));
    return r;
}

// shared inner loop: acc += A(64 rows) x W(64 cols), K=64, FFMA2 4x4 tile
__device__ __forceinline__ void mm64_acc(
    const float (*__restrict__ As)[68], const float (*__restrict__ Ws)[68],
    int tx, int ty, u64 acc[2][4])
{
    #pragma unroll
    for (int k = 0; k < 64; k++) {
        double2 a2 = *(const double2*)&As[k][ty * 4];
        u64 a01 = __double_as_longlong(a2.x);
        u64 a23 = __double_as_longlong(a2.y);
        float4 b4 = *(const float4*)&Ws[k][tx * 4];
        u64 b0 = pack2(b4.x, b4.x);
        u64 b1 = pack2(b4.y, b4.y);
        u64 b2 = pack2(b4.z, b4.z);
        u64 b3 = pack2(b4.w, b4.w);
        acc[0][0] = fma2(a01, b0, acc[0][0]);
        acc[0][1] = fma2(a01, b1, acc[0][1]);
        acc[0][2] = fma2(a01, b2, acc[0][2]);
        acc[0][3] = fma2(a01, b3, acc[0][3]);
        acc[1][0] = fma2(a23, b0, acc[1][0]);
        acc[1][1] = fma2(a23, b1, acc[1][1]);
        acc[1][2] = fma2(a23, b2, acc[1][2]);
        acc[1][3] = fma2(a23, b3, acc[1][3]);
    }
}

// ---------------- conv 3x3 + BN + ReLU -> [B,S,D] ----------------
__global__ __launch_bounds__(256) void conv_bn_relu(
    const float* __restrict__ x, const float* __restrict__ w,
    const float* __restrict__ cb, const float* __restrict__ gma,
    const float* __restrict__ bta, const float* __restrict__ mean,
    const float* __restrict__ var, float* __restrict__ y)
{
    int idx = blockIdx.x * 256 + threadIdx.x;
    if (idx >= BSR * DD) return;
    int d = idx & 63;
    int s = (idx >> 6) % SB;
    int b = idx / (SB * DD);
    int hh = s / WWD, ww = s % WWD;
    float sum = cb[d];
    #pragma unroll
    for (int ci = 0; ci < 3; ci++) {
        #pragma unroll
        for (int kh = 0; kh < 3; kh++) {
            int ih = hh + kh - 1;
            if ((unsigned)ih >= HH) continue;
            #pragma unroll
            for (int kw = 0; kw < 3; kw++) {
                int iw = ww + kw - 1;
                if ((unsigned)iw >= WWD) continue;
                sum += x[((b * CC + ci) * HH + ih) * WWD + iw] *
                       w[((d * CC + ci) * 3 + kh) * 3 + kw];
            }
        }
    }
    sum = (sum - mean[d]) * rsqrtf(var[d] + EPSV) * gma[d] + bta[d];
    y[idx] = fmaxf(sum, 0.0f);
}

// ---------------- gemm64: C[M,N] = A[M,64] @ W[N,64]^T + bias ----------------
template<int RELU>
__global__ __launch_bounds__(256) void gemm64(
    const float* __restrict__ A, const float* __restrict__ W,
    const float* __restrict__ bias, float* __restrict__ C, int N)
{
    __shared__ __align__(16) float As[64][68];
    __shared__ __align__(16) float Ws[64][68];
    int tid = threadIdx.x;
    int rowBase = blockIdx.y * 64;
    int nBase = blockIdx.x * 64;

    int r = tid >> 2, qd = tid & 3;
    {
        const float* ap = A + (rowBase + r) * 64 + qd * 4;
        #pragma unroll
        for (int j = 0; j < 4; j++) {
            float4 v = *(const float4*)(ap + j * 16);
            int k = qd * 4 + j * 16;
            As[k][r] = v.x; As[k + 1][r] = v.y; As[k + 2][r] = v.z; As[k + 3][r] = v.w;
        }
        int n = nBase + r;
        if (n < N) {
            const float* wp = W + n * 64 + qd * 4;
            #pragma unroll
            for (int j = 0; j < 4; j++) {
                float4 v = *(const float4*)(wp + j * 16);
                int k = qd * 4 + j * 16;
                Ws[k][r] = v.x; Ws[k + 1][r] = v.y; Ws[k + 2][r] = v.z; Ws[k + 3][r] = v.w;
            }
        } else {
            #pragma unroll
            for (int j = 0; j < 4; j++) {
                int k = qd * 4 + j * 16;
                Ws[k][r] = 0.f; Ws[k + 1][r] = 0.f; Ws[k + 2][r] = 0.f; Ws[k + 3][r] = 0.f;
            }
        }
    }
    __syncthreads();

    int tx = tid & 15, ty = tid >> 4;
    u64 acc[2][4] = {};
    mm64_acc(As, Ws, tx, ty, acc);

    float rv[4][4];
    #pragma unroll
    for (int v = 0; v < 4; v++) {
        unpack2(acc[0][v], rv[0][v], rv[1][v]);
        unpack2(acc[1][v], rv[2][v], rv[3][v]);
    }
    #pragma unroll
    for (int u = 0; u < 4; u++) {
        int row = rowBase + ty * 4 + u;
        #pragma unroll
        for (int v = 0; v < 4; v++) {
            int n = nBase + tx * 4 + v;
            if (n < N) {
                float val = rv[u][v] + bias[n];
                if (RELU) val = fmaxf(val, 0.0f);
                C[row * N + n] = val;
            }
        }
    }
}

// ---------------- gemm64_ln: Y = LN(Y + A @ W^T + bias), fused ----------------
__global__ __launch_bounds__(256) void gemm64_ln(
    const float* __restrict__ A, const float* __restrict__ W,
    const float* __restrict__ bias, float* __restrict__ Y,
    const float* __restrict__ gam, const float* __restrict__ bet)
{
    __shared__ __align__(16) float As[64][68];
    __shared__ __align__(16) float Ws[64][68];
    int tid = threadIdx.x;
    int rowBase = blockIdx.x * 64;

    int r = tid >> 2, qd = tid & 3;
    {
        const float* ap = A + (rowBase + r) * 64 + qd * 4;
        const float* wp = W + r * 64 + qd * 4;
        #pragma unroll
        for (int j = 0; j < 4; j++) {
            float4 va = *(const float4*)(ap + j * 16);
            float4 vw = *(const float4*)(wp + j * 16);
            int k = qd * 4 + j * 16;
            As[k][r] = va.x; As[k + 1][r] = va.y; As[k + 2][r] = va.z; As[k + 3][r] = va.w;
            Ws[k][r] = vw.x; Ws[k + 1][r] = vw.y; Ws[k + 2][r] = vw.z; Ws[k + 3][r] = vw.w;
        }
    }
    __syncthreads();

    int tx = tid & 15, ty = tid >> 4;
    u64 acc[2][4] = {};
    mm64_acc(As, Ws, tx, ty, acc);
    float rv[4][4];
    #pragma unroll
    for (int v = 0; v < 4; v++) {
        unpack2(acc[0][v], rv[0][v], rv[1][v]);
        unpack2(acc[1][v], rv[2][v], rv[3][v]);
    }
    __syncthreads();   // done reading Ws; reuse as Z

    #pragma unroll
    for (int u = 0; u < 4; u++) {
        int row = ty * 4 + u;
        float4 yv = *(const float4*)&Y[(rowBase + row) * 64 + tx * 4];
        Ws[row][tx * 4 + 0] = rv[u][0] + bias[tx * 4 + 0] + yv.x;
        Ws[row][tx * 4 + 1] = rv[u][1] + bias[tx * 4 + 1] + yv.y;
        Ws[row][tx * 4 + 2] = rv[u][2] + bias[tx * 4 + 2] + yv.z;
        Ws[row][tx * 4 + 3] = rv[u][3] + bias[tx * 4 + 3] + yv.w;
    }
    __syncthreads();

    int wid = tid >> 5, lane = tid & 31;
    #pragma unroll 1
    for (int i = 0; i < 8; i++) {
        int row = wid * 8 + i;
        float z0 = Ws[row][lane];
        float z1 = Ws[row][lane + 32];
        float s = z0 + z1;
        float ss = z0 * z0 + z1 * z1;
        #pragma unroll
        for (int off = 16; off; off >>= 1) {
            s  += __shfl_xor_sync(0xFFFFFFFFu, s, off);
            ss += __shfl_xor_sync(0xFFFFFFFFu, ss, off);
        }
        float mean = s * (1.0f / 64.0f);
        float var = ss * (1.0f / 64.0f) - mean * mean;
        float inv = rsqrtf(var + EPSV);
        Y[(rowBase + row) * 64 + lane]      = (z0 - mean) * inv * gam[lane]      + bet[lane];
        Y[(rowBase + row) * 64 + 32 + lane] = (z1 - mean) * inv * gam[32 + lane] + bet[32 + lane];
    }
}

// ============================================================================
// ffn_fused: partial[z] = relu(Y @ W1_z^T + b1_z) @ W2_z^T  (one kernel)
// grid (BSR/64, ZSPL), 256 threads, dynamic smem 3*64*68*4 = 52224 B.
// Y tile resident; W1/W2 chunks share one stage buffer; ff1 chunk in smem.
// ============================================================================
__global__ __launch_bounds__(256, 4) void ffn_fused(
    const float* __restrict__ Y, const float* __restrict__ W1,
    const float* __restrict__ b1, const float* __restrict__ W2,
    float* __restrict__ Cpart)
{
    extern __shared__ __align__(16) float smraw[];
    float (*Ys)[68]  = (float(*)[68])smraw;               // A for GEMM1
    float (*Wst)[68] = (float(*)[68])(smraw + 64 * 68);   // W1c, then W2c
    float (*F1)[68]  = (float(*)[68])(smraw + 2 * 64 * 68); // ff1 chunk [k][row]

    int tid = threadIdx.x;
    int rowBase = blockIdx.x * 64;
    int z = blockIdx.y;
    int r = tid >> 2, qd = tid & 3;
    int tx = tid & 15, ty = tid >> 4;

    // stage Y tile once
    {
        const float* yp = Y + (rowBase + r) * 64 + qd * 4;
        #pragma unroll
        for (int j = 0; j < 4; j++) {
            float4 v = *(const float4*)(yp + j * 16);
            int k = qd * 4 + j * 16;
            Ys[k][r] = v.x; Ys[k + 1][r] = v.y; Ys[k + 2][r] = v.z; Ys[k + 3][r] = v.w;
        }
    }

    u64 acc2[2][4] = {};   // lin2 partial accumulators (carried over chunks)

    #pragma unroll 1
    for (int c = 0; c < FFD / (ZSPL * 64); c++) {       // 4 chunks
        int kcol = z * (FFD / ZSPL) + c * 64;           // global ff1-col base
        __syncthreads();   // prior chunk's GEMM2 done with Wst/F1
        // stage W1 chunk: rows kcol..kcol+63 of W1[FFD][64]
        {
            const float* wp = W1 + (kcol + r) * 64 + qd * 4;
            #pragma unroll
            for (int j = 0; j < 4; j++) {
                float4 v = *(const float4*)(wp + j * 16);
                int k = qd * 4 + j * 16;
                Wst[k][r] = v.x; Wst[k + 1][r] = v.y; Wst[k + 2][r] = v.z; Wst[k + 3][r] = v.w;
            }
        }
        __syncthreads();

        // GEMM1: ff1c = Ys @ W1c^T
        u64 a1[2][4] = {};
        mm64_acc((const float(*)[68])Ys, (const float(*)[68])Wst, tx, ty, a1);
        float rv[4][4];
        #pragma unroll
        for (int v = 0; v < 4; v++) {
            unpack2(a1[0][v], rv[0][v], rv[1][v]);
            unpack2(a1[1][v], rv[2][v], rv[3][v]);
        }
        __syncthreads();   // done reading Wst (W1c)

        // relu + bias, transpose-store ff1c to F1[k'][row]; stage W2 chunk
        {
            float4 bb = *(const float4*)(b1 + kcol + tx * 4);
            float bv[4] = {bb.x, bb.y, bb.z, bb.w};
            #pragma unroll
            for (int u = 0; u < 4; u++) {
                int row = ty * 4 + u;
                #pragma unroll
                for (int v = 0; v < 4; v++)
                    F1[tx * 4 + v][row] = fmaxf(rv[u][v] + bv[v], 0.0f);
            }
            const float* wp = W2 + r * FFD + kcol + qd * 4;
            #pragma unroll
            for (int j = 0; j < 4; j++) {
                float4 v = *(const float4*)(wp + j * 16);
                int k = qd * 4 + j * 16;
                Wst[k][r] = v.x; Wst[k + 1][r] = v.y; Wst[k + 2][r] = v.z; Wst[k + 3][r] = v.w;
            }
        }
        __syncthreads();

        // GEMM2: acc2 += ff1c @ W2c^T
        mm64_acc((const float(*)[68])F1, (const float(*)[68])Wst, tx, ty, acc2);
    }

    // write partial
    float* Cp = Cpart + z * (BSR * 64);
    float rv2[4][4];
    #pragma unroll
    for (int v = 0; v < 4; v++) {
        unpack2(acc2[0][v], rv2[0][v], rv2[1][v]);
        unpack2(acc2[1][v], rv2[2][v], rv2[3][v]);
    }
    #pragma unroll
    for (int u = 0; u < 4; u++) {
        int row = rowBase + ty * 4 + u;
        *(float4*)&Cp[row * 64 + tx * 4] =
            make_float4(rv2[u][0], rv2[u][1], rv2[u][2], rv2[u][3]);
    }
}

// ---------------- merge split-K partials + bias + residual + LN ----------------
__global__ __launch_bounds__(256) void add_ln_ff(
    float* __restrict__ Y, const float* __restrict__ part,
    const float* __restrict__ bias,
    const float* __restrict__ gam, const float* __restrict__ bet)
{
    int row = blockIdx.x * 8 + (threadIdx.x >> 5);
    int lane = threadIdx.x & 31;
    float z0 = Y[row * 64 + lane]      + bias[lane];
    float z1 = Y[row * 64 + 32 + lane] + bias[32 + lane];
    #pragma unroll
    for (int z = 0; z < ZSPL; z++) {
        z0 += part[z * (BSR * 64) + row * 64 + lane];
        z1 += part[z * (BSR * 64) + row * 64 + 32 + lane];
    }
    float s = z0 + z1;
    float ss = z0 * z0 + z1 * z1;
    #pragma unroll
    for (int off = 16; off; off >>= 1) {
        s  += __shfl_xor_sync(0xFFFFFFFFu, s, off);
        ss += __shfl_xor_sync(0xFFFFFFFFu, ss, off);
    }
    float mean = s * (1.0f / 64.0f);
    float var = ss * (1.0f / 64.0f) - mean * mean;
    float inv = rsqrtf(var + EPSV);
    Y[row * 64 + lane]      = (z0 - mean) * inv * gam[lane]      + bet[lane];
    Y[row * 64 + 32 + lane] = (z1 - mean) * inv * gam[32 + lane] + bet[32 + lane];
}

// ---------------- attention: unshifted softmax (R13, unchanged) ---------------
__global__ __launch_bounds__(384) void attention_kernel(
    const float* __restrict__ qkv, float* __restrict__ o)
{
    __shared__ __align__(16) float Kt[3][128][8];
    __shared__ __align__(16) float Vt[3][128][8];
    __shared__ float Ss[2][128];
    __shared__ float Accs[2][128][8];

    int tid = threadIdx.x;
    int g = tid >> 7;          // 0..2
    int t = tid & 127;
    int bh = blockIdx.x;
    int b = bh >> 3, h = bh & 7;
    int qbase = blockIdx.y * 128;
    int srow = b * SB + qbase + t;

    const float QS = 0.35355339059327373f * 1.4426950408889634f;
    const float* qp = qkv + srow * 192 + h * 8;
    float4 qa = *(const float4*)qp;
    float4 qb = *(const float4*)(qp + 4);
    u64 q01 = pack2(qa.x * QS, qa.y * QS);
    u64 q23 = pack2(qa.z * QS, qa.w * QS);
    u64 q45 = pack2(qb.x * QS, qb.y * QS);
    u64 q67 = pack2(qb.z * QS, qb.w * QS);

    float sum = 0.0f;
    u64 a01 = 0, a23 = 0, a45 = 0, a67 = 0;

    for (int tile = g; tile < 18; tile += 3) {
        int krow = b * SB + tile * 128 + t;
        const float* kp = qkv + krow * 192 + 64 + h * 8;
        float4 k0 = *(const float4*)kp;
        float4 k1 = *(const float4*)(kp + 4);
        float4 v0 = *(const float4*)(kp + 64);
        float4 v1 = *(const float4*)(kp + 68);
        *(float4*)&Kt[g][t][0] = k0; *(float4*)&Kt[g][t][4] = k1;
        *(float4*)&Vt[g][t][0] = v0; *(float4*)&Vt[g][t][4] = v1;
        asm volatile("bar.sync %0, 128;" :: "r"(g + 1) : "memory");

        #pragma unroll 4
        for (int kk = 0; kk < 128; kk++) {
            double2 ka = *(const double2*)&Kt[g][kk][0];
            double2 kb2 = *(const double2*)&Kt[g][kk][4];
            u64 d = mul2(q01, __double_as_longlong(ka.x));
            d = fma2(q23, __double_as_longlong(ka.y), d);
            d = fma2(q45, __double_as_longlong(kb2.x), d);
            d = fma2(q67, __double_as_longlong(kb2.y), d);
            float lo, hi;
            unpack2(d, lo, hi);
            float e = ex2f(lo + hi);
            sum += e;
            u64 pe = pack2(e, e);
            double2 va = *(const double2*)&Vt[g][kk][0];
            double2 vb2 = *(const double2*)&Vt[g][kk][4];
            a01 = fma2(pe, __double_as_longlong(va.x), a01);
            a23 = fma2(pe, __double_as_longlong(va.y), a23);
            a45 = fma2(pe, __double_as_longlong(vb2.x), a45);
            a67 = fma2(pe, __double_as_longlong(vb2.y), a67);
        }
        asm volatile("bar.sync %0, 128;" :: "r"(g + 1) : "memory");
    }

    float av[8];
    unpack2(a01, av[0], av[1]);
    unpack2(a23, av[2], av[3]);
    unpack2(a45, av[4], av[5]);
    unpack2(a67, av[6], av[7]);

    if (g > 0) {
        Ss[g - 1][t] = sum;
        #pragma unroll
        for (int j = 0; j < 8; j++) Accs[g - 1][t][j] = av[j];
    }
    __syncthreads();
    if (g == 0) {
        sum += Ss[0][t] + Ss[1][t];
        #pragma unroll
        for (int j = 0; j < 8; j++)
            av[j] += Accs[0][t][j] + Accs[1][t][j];
        float inv = 1.0f / sum;
        float* op = o + srow * 64 + h * 8;
        float4 o0 = make_float4(av[0]*inv, av[1]*inv, av[2]*inv, av[3]*inv);
        float4 o1 = make_float4(av[4]*inv, av[5]*inv, av[6]*inv, av[7]*inv);
        *(float4*)op = o0;
        *(float4*)(op + 4) = o1;
    }
}

// ---------------- final softmax over 441 + transpose to [B,441,S] ----------
__global__ __launch_bounds__(128) void softmax_t_kernel(
    const float* __restrict__ sc, float* __restrict__ outK)
{
    __shared__ float red[128];
    int row = blockIdx.x;
    int b = row / SB, s = row % SB;
    int tid = threadIdx.x;
    float v[4];
    float mx = -1e30f;
    #pragma unroll
    for (int i = 0; i < 4; i++) {
        int p = tid + i * 128;
        v[i] = (p < KK2) ? sc[row * KK2 + p] : -1e30f;
        mx = fmaxf(mx, v[i]);
    }
    red[tid] = mx; __syncthreads();
    for (int o = 64; o; o >>= 1) { if (tid < o) red[tid] = fmaxf(red[tid], red[tid + o]); __syncthreads(); }
    float m = red[0]; __syncthreads();
    float sum = 0.0f;
    #pragma unroll
    for (int i = 0; i < 4; i++) {
        int p = tid + i * 128;
        v[i] = (p < KK2) ? __expf(v[i] - m) : 0.0f;
        sum += v[i];
    }
    red[tid] = sum; __syncthreads();
    for (int o = 64; o; o >>= 1) { if (tid < o) red[tid] += red[tid + o]; __syncthreads(); }
    float inv = 1.0f / red[0];
    #pragma unroll
    for (int i = 0; i < 4; i++) {
        int p = tid + i * 128;
        if (p < KK2) outK[(b * KK2 + p) * SB + s] = v[i] * inv;
    }
}

// ---------------- apply predicted kernel (reflect pad), 128-thr blocks --------
__global__ __launch_bounds__(128) void apply_kernel(
    const float* __restrict__ x, const float* __restrict__ kern, float* __restrict__ out)
{
    int idx = blockIdx.x * 128 + threadIdx.x;
    if (idx >= BB * CC * HH * WWD) return;
    int ww = idx % WWD;
    int hh = (idx / WWD) % HH;
    int c = (idx / (HH * WWD)) % CC;
    int b = idx / (CC * HH * WWD);
    const float* kb = kern + b * KK2 * SB + hh * WWD + ww;
    const float* xb = x + (b * CC + c) * HH * WWD;
    float acc = 0.0f;
    #pragma unroll 1
    for (int kh = 0; kh < KS; kh++) {
        int ih = hh + kh - 10;
        if (ih < 0) ih = -ih;
        else if (ih >= HH) ih = 2 * HH - 2 - ih;
        const float* xr = xb + ih * WWD;
        #pragma unroll
        for (int kw = 0; kw < KS; kw++) {
            int iw = ww + kw - 10;
            if (iw < 0) iw = -iw;
            else if (iw >= WWD) iw = 2 * WWD - 2 - iw;
            acc = fmaf(xr[iw], kb[(kh * KS + kw) * SB], acc);
        }
    }
    out[idx] = acc;
}

// ---------------- host launcher ----------------
extern "C" void kernel_launch(void* const* d_in, const int* in_sizes, int n_in,
                              void* d_out, int out_size)
{
    const float* x        = (const float*)d_in[0];
    const float* conv1_w  = (const float*)d_in[1];
    const float* conv1_b  = (const float*)d_in[2];
    const float* bn_gamma = (const float*)d_in[3];
    const float* bn_beta  = (const float*)d_in[4];
    const float* bn_mean  = (const float*)d_in[5];
    const float* bn_var   = (const float*)d_in[6];
    const float* attn_in_w  = (const float*)d_in[7];
    const float* attn_in_b  = (const float*)d_in[8];
    const float* attn_out_w = (const float*)d_in[9];
    const float* attn_out_b = (const float*)d_in[10];
    const float* lin1_w   = (const float*)d_in[11];
    const float* lin1_b   = (const float*)d_in[12];
    const float* lin2_w   = (const float*)d_in[13];
    const float* lin2_b   = (const float*)d_in[14];
    const float* ln1_g    = (const float*)d_in[15];
    const float* ln1_b    = (const float*)d_in[16];
    const float* ln2_g    = (const float*)d_in[17];
    const float* ln2_b    = (const float*)d_in[18];
    const float* last_w   = (const float*)d_in[19];
    const float* last_b   = (const float*)d_in[20];

    float* out = (float*)d_out;
    float* kern = out + BB * CC * HH * WWD;

    float *py, *pqkv, *pattno, *ppart, *pff;
    cudaGetSymbolAddress((void**)&py, g_y);
    cudaGetSymbolAddress((void**)&pqkv, g_qkv);
    cudaGetSymbolAddress((void**)&pattno, g_attno);
    cudaGetSymbolAddress((void**)&ppart, g_part);
    cudaGetSymbolAddress((void**)&pff, g_ff);

    const int FFN_SMEM = 3 * 64 * 68 * sizeof(float);   // 52224 B
    cudaFuncSetAttribute(ffn_fused, cudaFuncAttributeMaxDynamicSharedMemorySize, FFN_SMEM);

    conv_bn_relu<<<(BSR * DD + 255) / 256, 256>>>(x, conv1_w, conv1_b, bn_gamma,
                                                  bn_beta, bn_mean, bn_var, py);

    for (int l = 0; l < NLAYER; l++) {
        // qkv = y @ Win^T + b   [4608,192]
        gemm64<0><<<dim3(3, BSR / 64), 256>>>(
            py, attn_in_w + l * 192 * DD, attn_in_b + l * 192, pqkv, 192);
        // attention -> attno [4608,64]
        attention_kernel<<<dim3(BB * NHH, SB / 128), 384>>>(pqkv, pattno);
        // y = LN(y + attno @ Wout^T + b)   (fused)
        gemm64_ln<<<BSR / 64, 256>>>(
            pattno, attn_out_w + l * DD * DD, attn_out_b + l * DD, py,
            ln1_g + l * DD, ln1_b + l * DD);
        // FFN: partial[z] = relu(y @ W1_z^T + b1_z) @ W2_z^T   (fused, one kernel)
        ffn_fused<<<dim3(BSR / 64, ZSPL), 256, FFN_SMEM>>>(
            py, lin1_w + l * FFD * DD, lin1_b + l * FFD,
            lin2_w + l * DD * FFD, ppart);
        // y = LN(y + sum(partials) + b2)
        add_ln_ff<<<BSR / 8, 256>>>(py, ppart, lin2_b + l * DD,
                                    ln2_g + l * DD, ln2_b + l * DD);
    }

    // scores = y @ last_w^T + last_b  [4608,441]
    gemm64<0><<<dim3((KK2 + 63) / 64, BSR / 64), 256>>>(py, last_w, last_b, pff, KK2);
    softmax_t_kernel<<<BSR, 128>>>(pff, kern);
    apply_kernel<<<(BB * CC * HH * WWD + 127) / 128, 128>>>(x, kern, out);
}